// round 4
// baseline (speedup 1.0000x reference)
#include <cuda_runtime.h>
#include <cstdint>

#define NN 50000
#define EMAX 500000
#define HID 160

// ---------------- scratch (static device globals; no allocation) ----------------
__device__ float g_feat[NN * HID];
__device__ float g_h1[NN * HID];
__device__ float g_mean[NN * HID];
__device__ float g_h2[NN * HID];
__device__ int g_deg[NN];
__device__ int g_offs[NN + 1];
__device__ int g_cursor[NN];
__device__ int g_csr[EMAX];
__device__ int g_is64;
// tf32-preconverted weights: W_des | W_tw | W_txt | W_in | W_l | W_r | W_o1
__device__ uint32_t g_wtf[3 * 24576 + 4 * 25600];

__device__ __forceinline__ float lrelu(float x) { return x > 0.f ? x : 0.01f * x; }

__device__ __forceinline__ uint32_t f2tf32(float x) {
    uint32_t u;
    asm("cvt.rna.tf32.f32 %0, %1;" : "=r"(u) : "f"(x));
    return u;
}

__device__ __forceinline__ void cp16(void* dst_smem, const void* src, bool pred) {
    uint32_t d = (uint32_t)__cvta_generic_to_shared(dst_smem);
    int sz = pred ? 16 : 0;
    asm volatile("cp.async.cg.shared.global [%0], [%1], 16, %2;" :: "r"(d), "l"(src), "r"(sz));
}

// ---------------- weight preconversion (fp32 -> tf32 bits, RNA) ----------------
struct WConvArgs {
    const float* src[7];
    int off[8];   // prefix offsets into g_wtf
};

__global__ void wconv_kernel(WConvArgs a) {
    int i = blockIdx.x * 256 + threadIdx.x;
    #pragma unroll
    for (int s = 0; s < 7; s++) {
        if (i >= a.off[s] && i < a.off[s + 1])
            g_wtf[i] = f2tf32(a.src[s][i - a.off[s]]);
    }
}

// Edge index may be int64 (as written in reference) or int32 (JAX canonicalization).
__device__ __forceinline__ int edge_val(const void* ei, int idx) {
    if (g_is64) return (int)((const long long*)ei)[idx];
    return ((const int*)ei)[idx];
}

__global__ void detect_kernel(const void* ei, int E) {
    __shared__ int any_hi;
    int t = threadIdx.x;
    if (t == 0) any_hi = 0;
    __syncthreads();
    const unsigned long long* p = (const unsigned long long*)ei;
    int n = E < 1024 ? E : 1024;
    unsigned long long acc = 0;
    for (int i = t; i < n; i += 256) acc |= p[i];
    if (acc > 0xFFFFFFFFull) atomicOr(&any_hi, 1);
    __syncthreads();
    if (t == 0) g_is64 = any_hi ? 0 : 1;
}

// ---------------- tf32 tensor-core GEMM core ----------------
// BM=128, BN=32, BK=32; 128 threads = 4 warps; warp tile 32m x 32n.
// Double-buffered cp.async. A converted fp32->tf32 at fragment load (RNA);
// W is preconverted tf32 bits in gmem, loaded raw.
template <bool LEAKY>
__device__ __forceinline__ void gemm_core(
    const float* __restrict__ A1, const uint32_t* __restrict__ W1,
    const float* __restrict__ A2, const uint32_t* __restrict__ W2,
    const float* __restrict__ bias, float* __restrict__ C,
    int M, int K, int ldW, int ldC, int cOff, bool dual)
{
    // As[m][k] stride 36: frag bank = (4m + k) % 32, conflict-free.
    // Ws[k][n] stride 40: frag bank = (8k + n) % 32, conflict-free.
    __shared__ __align__(16) float As[2][128][36];
    __shared__ __align__(16) uint32_t Ws[2][32][40];

    const int t = threadIdx.x;
    const int warp = t >> 5;
    const int lane = t & 31;
    const int g = lane >> 2;
    const int tg = lane & 3;
    const int blockRow = blockIdx.x * 128;
    const int bn = blockIdx.y * 32;
    const int warpRow = warp * 32;

    // W loader: thread t -> k-row t>>2 (0..31), 32B col-chunk (t&3)*8
    const int wrow = t >> 2;
    const int wcol = (t & 3) * 8;

    const int nkpp = K >> 5;
    const int nchunks = dual ? (nkpp << 1) : nkpp;

    auto issue = [&](int c) {
        int pass = (c >= nkpp) ? 1 : 0;
        int k0 = (pass ? c - nkpp : c) << 5;
        const float* __restrict__ A = pass ? A2 : A1;
        const uint32_t* __restrict__ W = pass ? W2 : W1;
        int buf = c & 1;
        int gr = blockRow + t;                  // one row per thread
        const float* src = A + (size_t)gr * K + k0;
        bool p = gr < M;
        #pragma unroll
        for (int j = 0; j < 8; j++)
            cp16(&As[buf][t][j * 4], src + j * 4, p);
        const uint32_t* wsrc = W + (size_t)(k0 + wrow) * ldW + bn + wcol;
        cp16(&Ws[buf][wrow][wcol], wsrc, true);
        cp16(&Ws[buf][wrow][wcol + 4], wsrc + 4, true);
        asm volatile("cp.async.commit_group;");
    };

    float acc[2][4][4] = {};

    issue(0);
    for (int c = 0; c < nchunks; c++) {
        if (c + 1 < nchunks) {
            issue(c + 1);
            asm volatile("cp.async.wait_group 1;");
        } else {
            asm volatile("cp.async.wait_group 0;");
        }
        __syncthreads();
        const int buf = c & 1;
        #pragma unroll
        for (int kk = 0; kk < 32; kk += 8) {
            uint32_t a[2][4];
            #pragma unroll
            for (int mt = 0; mt < 2; mt++) {
                const int r = warpRow + mt * 16 + g;
                a[mt][0] = f2tf32(As[buf][r][kk + tg]);
                a[mt][1] = f2tf32(As[buf][r + 8][kk + tg]);
                a[mt][2] = f2tf32(As[buf][r][kk + tg + 4]);
                a[mt][3] = f2tf32(As[buf][r + 8][kk + tg + 4]);
            }
            #pragma unroll
            for (int nt = 0; nt < 4; nt++) {
                uint32_t b0 = Ws[buf][kk + tg][nt * 8 + g];
                uint32_t b1 = Ws[buf][kk + tg + 4][nt * 8 + g];
                #pragma unroll
                for (int mt = 0; mt < 2; mt++) {
                    float* cc = acc[mt][nt];
                    asm volatile(
                        "mma.sync.aligned.m16n8k8.row.col.f32.tf32.tf32.f32 "
                        "{%0,%1,%2,%3}, {%4,%5,%6,%7}, {%8,%9}, {%0,%1,%2,%3};"
                        : "+f"(cc[0]), "+f"(cc[1]), "+f"(cc[2]), "+f"(cc[3])
                        : "r"(a[mt][0]), "r"(a[mt][1]), "r"(a[mt][2]), "r"(a[mt][3]),
                          "r"(b0), "r"(b1));
                }
            }
        }
        __syncthreads();
    }

    // ---- epilogue ----
    #pragma unroll
    for (int nt = 0; nt < 4; nt++) {
        int lc = nt * 8 + 2 * tg;
        float b0 = bias[bn + lc];
        float b1 = bias[bn + lc + 1];
        #pragma unroll
        for (int mt = 0; mt < 2; mt++) {
            float* cc = acc[mt][nt];
            int r0 = blockRow + warpRow + mt * 16 + g;
            int r1 = r0 + 8;
            float v00 = cc[0] + b0, v01 = cc[1] + b1;
            float v10 = cc[2] + b0, v11 = cc[3] + b1;
            if (LEAKY) {
                v00 = lrelu(v00); v01 = lrelu(v01);
                v10 = lrelu(v10); v11 = lrelu(v11);
            }
            if (r0 < M)
                *(float2*)(C + (size_t)r0 * ldC + cOff + bn + lc) = make_float2(v00, v01);
            if (r1 < M)
                *(float2*)(C + (size_t)r1 * ldC + cOff + bn + lc) = make_float2(v10, v11);
        }
    }
}

// fused 3-way projection: blockIdx.z selects (A, tf32-W, b, column offset)
struct ProjArgs {
    const float* A[3];
    const uint32_t* W[3];
    const float* b[3];
    int off[3];
};

__global__ void __launch_bounds__(128) proj_kernel(ProjArgs pa, float* __restrict__ C,
                                                   int M, int K) {
    int z = blockIdx.z;
    gemm_core<true>(pa.A[z], pa.W[z], nullptr, nullptr, pa.b[z], C,
                    M, K, 32, HID, pa.off[z], false);
}

template <bool DUAL, bool LEAKY>
__global__ void __launch_bounds__(128) gemm_tc_kernel(
    const float* __restrict__ A1, const uint32_t* __restrict__ W1,
    const float* __restrict__ A2, const uint32_t* __restrict__ W2,
    const float* __restrict__ bias, float* __restrict__ C,
    int M, int K, int ldW, int ldC, int cOff) {
    gemm_core<LEAKY>(A1, W1, A2, W2, bias, C, M, K, ldW, ldC, cOff, DUAL);
}

// ---------------- small feature projections: num_prop (6->32), num_category (11->32)
__global__ void __launch_bounds__(256) feat_small_kernel(
    const float* __restrict__ np, const float* __restrict__ nc,
    const float* __restrict__ Wnp, const float* __restrict__ bnp,
    const float* __restrict__ Wnc, const float* __restrict__ bnc,
    float* __restrict__ out)
{
    __shared__ float sWnp[6 * 32];
    __shared__ float sWnc[11 * 32];
    __shared__ float sb[64];
    int t = threadIdx.x;
    for (int i = t; i < 192; i += 256) sWnp[i] = Wnp[i];
    for (int i = t; i < 352; i += 256) sWnc[i] = Wnc[i];
    if (t < 32) sb[t] = bnp[t];
    else if (t < 64) sb[t] = bnc[t - 32];
    __syncthreads();

    int node = blockIdx.x * 8 + (t >> 5);
    int lane = t & 31;
    if (node >= NN) return;

    float a = sb[lane], c = sb[32 + lane];
    #pragma unroll
    for (int k = 0; k < 6; k++) a += np[(size_t)node * 6 + k] * sWnp[k * 32 + lane];
    #pragma unroll
    for (int k = 0; k < 11; k++) c += nc[(size_t)node * 11 + k] * sWnc[k * 32 + lane];
    out[(size_t)node * HID + lane] = lrelu(a);
    out[(size_t)node * HID + 32 + lane] = lrelu(c);
}

// ---------------- CSR build ----------------
__global__ void zero_deg_kernel() {
    int i = blockIdx.x * blockDim.x + threadIdx.x;
    if (i < NN) g_deg[i] = 0;
}

__global__ void count_deg_kernel(const void* __restrict__ ei, int E) {
    int e = blockIdx.x * blockDim.x + threadIdx.x;
    if (e < E) atomicAdd(&g_deg[edge_val(ei, E + e)], 1);
}

__global__ void scan_kernel() {
    __shared__ int part[1024];
    int t = threadIdx.x;
    const int chunk = (NN + 1023) / 1024;
    int s0 = t * chunk;
    int s1 = s0 + chunk; if (s1 > NN) s1 = NN; if (s0 > NN) s0 = NN;
    int s = 0;
    for (int i = s0; i < s1; i++) s += g_deg[i];
    part[t] = s;
    __syncthreads();
    for (int d = 1; d < 1024; d <<= 1) {
        int v = (t >= d) ? part[t - d] : 0;
        __syncthreads();
        part[t] += v;
        __syncthreads();
    }
    int excl = t ? part[t - 1] : 0;
    for (int i = s0; i < s1; i++) {
        g_offs[i] = excl;
        g_cursor[i] = excl;
        excl += g_deg[i];
    }
    if (t == 1023) g_offs[NN] = part[1023];
}

__global__ void fill_csr_kernel(const void* __restrict__ ei, int E) {
    int e = blockIdx.x * blockDim.x + threadIdx.x;
    if (e < E) {
        int d = edge_val(ei, E + e);
        int p = atomicAdd(&g_cursor[d], 1);
        g_csr[p] = edge_val(ei, e);
    }
}

// ---------------- mean aggregation: one warp per node ----------------
__global__ void __launch_bounds__(256) agg_kernel(const float* __restrict__ h,
                                                  float* __restrict__ mean)
{
    int w = (blockIdx.x * blockDim.x + threadIdx.x) >> 5;
    int lane = threadIdx.x & 31;
    if (w >= NN) return;
    int beg = g_offs[w], end = g_offs[w + 1];
    float a0 = 0.f, a1 = 0.f, a2 = 0.f, a3 = 0.f, a4 = 0.f;
    for (int e = beg; e < end; e++) {
        const float* row = h + (size_t)g_csr[e] * HID;
        a0 += row[lane];
        a1 += row[lane + 32];
        a2 += row[lane + 64];
        a3 += row[lane + 96];
        a4 += row[lane + 128];
    }
    int deg = end - beg;
    float inv = 1.f / (float)(deg > 0 ? deg : 1);
    float* m = mean + (size_t)w * HID;
    m[lane]       = a0 * inv;
    m[lane + 32]  = a1 * inv;
    m[lane + 64]  = a2 * inv;
    m[lane + 96]  = a3 * inv;
    m[lane + 128] = a4 * inv;
}

// ---------------- final 160->2 head: one warp per node ----------------
__global__ void __launch_bounds__(256) out2_kernel(
    const float* __restrict__ em, const float* __restrict__ W,
    const float* __restrict__ b, float* __restrict__ out)
{
    __shared__ float sW[320];
    int t = threadIdx.x;
    for (int i = t; i < 320; i += 256) sW[i] = W[i];
    __syncthreads();
    int node = blockIdx.x * 8 + (t >> 5);
    int lane = t & 31;
    if (node >= NN) return;
    float a0 = 0.f, a1 = 0.f;
    #pragma unroll
    for (int c = 0; c < 5; c++) {
        int k = lane + 32 * c;
        float v = em[(size_t)node * HID + k];
        a0 += v * sW[k * 2];
        a1 += v * sW[k * 2 + 1];
    }
    #pragma unroll
    for (int o = 16; o > 0; o >>= 1) {
        a0 += __shfl_down_sync(0xffffffffu, a0, o);
        a1 += __shfl_down_sync(0xffffffffu, a1, o);
    }
    if (lane == 0) {
        out[(size_t)node * 2]     = a0 + b[0];
        out[(size_t)node * 2 + 1] = a1 + b[1];
    }
}

// ---------------- launch ----------------
extern "C" void kernel_launch(void* const* d_in, const int* in_sizes, int n_in,
                              void* d_out, int out_size)
{
    const float* x        = (const float*)d_in[0];
    const void*  ei       = d_in[1];
    const float* num_prop = (const float*)d_in[2];
    const float* num_cat  = (const float*)d_in[3];
    const float* des      = (const float*)d_in[4];
    const float* tw       = (const float*)d_in[5];
    const float* W_des = (const float*)d_in[6];  const float* b_des = (const float*)d_in[7];
    const float* W_tw  = (const float*)d_in[8];  const float* b_tw  = (const float*)d_in[9];
    const float* W_txt = (const float*)d_in[10]; const float* b_txt = (const float*)d_in[11];
    const float* W_np  = (const float*)d_in[12]; const float* b_np  = (const float*)d_in[13];
    const float* W_nc  = (const float*)d_in[14]; const float* b_nc  = (const float*)d_in[15];
    const float* W_in  = (const float*)d_in[16]; const float* b_in  = (const float*)d_in[17];
    const float* W_l   = (const float*)d_in[18]; const float* b_l   = (const float*)d_in[19];
    const float* W_r   = (const float*)d_in[20];
    const float* W_o1  = (const float*)d_in[21]; const float* b_o1  = (const float*)d_in[22];
    const float* W_o2  = (const float*)d_in[23]; const float* b_o2  = (const float*)d_in[24];

    int E = in_sizes[1] / 2;
    if (E > EMAX) E = EMAX;

    float *feat, *h1, *mean, *h2;
    uint32_t* wtf;
    cudaGetSymbolAddress((void**)&feat, g_feat);
    cudaGetSymbolAddress((void**)&h1, g_h1);
    cudaGetSymbolAddress((void**)&mean, g_mean);
    cudaGetSymbolAddress((void**)&h2, g_h2);
    cudaGetSymbolAddress((void**)&wtf, g_wtf);

    float* outp = (float*)d_out;            // [N, 2]
    float* em   = (float*)d_out + 2 * NN;   // [N, 160]

    // weight preconversion offsets: W_des | W_tw | W_txt | W_in | W_l | W_r | W_o1
    WConvArgs wa;
    wa.src[0] = W_des; wa.src[1] = W_tw; wa.src[2] = W_txt;
    wa.src[3] = W_in;  wa.src[4] = W_l;  wa.src[5] = W_r; wa.src[6] = W_o1;
    int sizes[7] = {24576, 24576, 24576, 25600, 25600, 25600, 25600};
    wa.off[0] = 0;
    for (int i = 0; i < 7; i++) wa.off[i + 1] = wa.off[i] + sizes[i];
    const uint32_t* tW_des = wtf + wa.off[0];
    const uint32_t* tW_tw  = wtf + wa.off[1];
    const uint32_t* tW_txt = wtf + wa.off[2];
    const uint32_t* tW_in  = wtf + wa.off[3];
    const uint32_t* tW_l   = wtf + wa.off[4];
    const uint32_t* tW_r   = wtf + wa.off[5];
    const uint32_t* tW_o1  = wtf + wa.off[6];
    wconv_kernel<<<(wa.off[7] + 255) / 256, 256>>>(wa);

    dim3 gProj((NN + 127) / 128, 1, 3);
    dim3 g128x5((NN + 127) / 128, 5);
    int gNode8 = (NN + 7) / 8;
    int gEdge = (E + 255) / 256;

    // feature encoder -> g_feat [N,160] (cols: n|c|d|tw|t)
    feat_small_kernel<<<gNode8, 256>>>(num_prop, num_cat, W_np, b_np, W_nc, b_nc, feat);

    ProjArgs pa;
    pa.A[0] = des; pa.W[0] = tW_des; pa.b[0] = b_des; pa.off[0] = 64;
    pa.A[1] = tw;  pa.W[1] = tW_tw;  pa.b[1] = b_tw;  pa.off[1] = 96;
    pa.A[2] = x;   pa.W[2] = tW_txt; pa.b[2] = b_txt; pa.off[2] = 128;
    proj_kernel<<<gProj, 128>>>(pa, feat, NN, 768);

    // h1 = leaky(feat @ W_in + b_in)
    gemm_tc_kernel<false, true><<<g128x5, 128>>>(feat, tW_in, nullptr, nullptr, b_in, h1, NN, HID, HID, HID, 0);

    // CSR build (per-launch, deterministic detection of edge dtype)
    detect_kernel<<<1, 256>>>(ei, E);
    zero_deg_kernel<<<(NN + 255) / 256, 256>>>();
    count_deg_kernel<<<gEdge, 256>>>(ei, E);
    scan_kernel<<<1, 1024>>>();
    fill_csr_kernel<<<gEdge, 256>>>(ei, E);

    // conv1: h2 = mean(h1) @ W_l + b_l + h1 @ W_r
    agg_kernel<<<gNode8, 256>>>(h1, mean);
    gemm_tc_kernel<true, false><<<g128x5, 128>>>(mean, tW_l, h1, tW_r, b_l, h2, NN, HID, HID, HID, 0);

    // conv2: h1 = mean(h2) @ W_l + b_l + h2 @ W_r
    agg_kernel<<<gNode8, 256>>>(h2, mean);
    gemm_tc_kernel<true, false><<<g128x5, 128>>>(mean, tW_l, h2, tW_r, b_l, h1, NN, HID, HID, HID, 0);

    // em = leaky(h1 @ W_o1 + b_o1), written directly into d_out
    gemm_tc_kernel<false, true><<<g128x5, 128>>>(h1, tW_o1, nullptr, nullptr, b_o1, em, NN, HID, HID, HID, 0);

    // out = em @ W_o2 + b_o2
    out2_kernel<<<gNode8, 256>>>(em, W_o2, b_o2, outp);
}

// round 5
// speedup vs baseline: 1.1454x; 1.1454x over previous
#include <cuda_runtime.h>
#include <cstdint>

#define NN 50000
#define EMAX 500000
#define HID 160

// ---------------- scratch (static device globals; no allocation) ----------------
__device__ float g_feat[NN * HID];
__device__ float g_h1[NN * HID];
__device__ float g_mean[NN * HID];
__device__ float g_h2[NN * HID];
__device__ int g_deg[NN];
__device__ int g_offs[NN + 1];
__device__ int g_cursor[NN];
__device__ int g_csr[EMAX];
__device__ int g_is64;
// tf32-preconverted weights: W_des | W_tw | W_txt | W_in | W_l | W_r | W_o1
__device__ uint32_t g_wtf[3 * 24576 + 4 * 25600];

__device__ __forceinline__ float lrelu(float x) { return x > 0.f ? x : 0.01f * x; }

__device__ __forceinline__ uint32_t f2tf32(float x) {
    uint32_t u;
    asm("cvt.rna.tf32.f32 %0, %1;" : "=r"(u) : "f"(x));
    return u;
}

__device__ __forceinline__ void cp16(void* dst_smem, const void* src, bool pred) {
    uint32_t d = (uint32_t)__cvta_generic_to_shared(dst_smem);
    int sz = pred ? 16 : 0;
    asm volatile("cp.async.cg.shared.global [%0], [%1], 16, %2;" :: "r"(d), "l"(src), "r"(sz));
}

// ---------------- weight preconversion (fp32 -> tf32 bits, RNA) ----------------
struct WConvArgs {
    const float* src[7];
    int off[8];
};

__global__ void wconv_kernel(WConvArgs a) {
    int i = blockIdx.x * 256 + threadIdx.x;
    #pragma unroll
    for (int s = 0; s < 7; s++) {
        if (i >= a.off[s] && i < a.off[s + 1])
            g_wtf[i] = f2tf32(a.src[s][i - a.off[s]]);
    }
}

// Edge index may be int64 (as written in reference) or int32 (JAX canonicalization).
__device__ __forceinline__ int edge_val(const void* ei, int idx) {
    if (g_is64) return (int)((const long long*)ei)[idx];
    return ((const int*)ei)[idx];
}

__global__ void detect_kernel(const void* ei, int E) {
    __shared__ int any_hi;
    int t = threadIdx.x;
    if (t == 0) any_hi = 0;
    __syncthreads();
    const unsigned long long* p = (const unsigned long long*)ei;
    int n = E < 1024 ? E : 1024;
    unsigned long long acc = 0;
    for (int i = t; i < n; i += 256) acc |= p[i];
    if (acc > 0xFFFFFFFFull) atomicOr(&any_hi, 1);
    __syncthreads();
    if (t == 0) g_is64 = any_hi ? 0 : 1;
}

// ---------------- tf32 tensor-core GEMM core (split-K-in-CTA) ----------------
// BM=128, BN=32, BK=32; 256 threads = 8 warps = 4 m-warps x 2 k-groups.
// Each k-group does half of each K-chunk's kk-steps into private accs;
// one smem reduction at the end. Warp tile 32m x 32n.
// A: fp32 in gmem, tf32-converted at fragment load. W: preconverted tf32 bits.
template <bool LEAKY>
__device__ __forceinline__ void gemm_core(
    const float* __restrict__ A1, const uint32_t* __restrict__ W1,
    const float* __restrict__ A2, const uint32_t* __restrict__ W2,
    const float* __restrict__ bias, float* __restrict__ C,
    int M, int K, int ldW, int ldC, int cOff, bool dual)
{
    // As[m][k] stride 36: frag bank = (4m + k) % 32, conflict-free.
    // Ws[k][n] stride 40: frag bank = (8k + n) % 32, conflict-free.
    __shared__ __align__(16) float As[2][128][36];
    __shared__ __align__(16) uint32_t Ws[2][32][40];

    const int t = threadIdx.x;
    const int warp = t >> 5;
    const int lane = t & 31;
    const int mwarp = warp & 3;
    const int kg = warp >> 2;
    const int g = lane >> 2;
    const int tg = lane & 3;
    const int blockRow = blockIdx.x * 128;
    const int bn = blockIdx.y * 32;
    const int warpRow = mwarp * 32;

    // A loader: thread t -> row t>>1 (0..127), 64B half (t&1)
    const int arow = t >> 1;
    const int acol = (t & 1) * 16;
    // W loader: thread t -> k-row t>>3 (0..31), 16B chunk (t&7)*4
    const int wrow = t >> 3;
    const int wcol = (t & 7) * 4;

    const int nkpp = K >> 5;
    const int nchunks = dual ? (nkpp << 1) : nkpp;

    auto issue = [&](int c) {
        int pass = (c >= nkpp) ? 1 : 0;
        int k0 = (pass ? c - nkpp : c) << 5;
        const float* __restrict__ A = pass ? A2 : A1;
        const uint32_t* __restrict__ W = pass ? W2 : W1;
        int buf = c & 1;
        int gr = blockRow + arow;
        const float* src = A + (size_t)gr * K + k0 + acol;
        bool p = gr < M;
        #pragma unroll
        for (int j = 0; j < 4; j++)
            cp16(&As[buf][arow][acol + j * 4], src + j * 4, p);
        const uint32_t* wsrc = W + (size_t)(k0 + wrow) * ldW + bn + wcol;
        cp16(&Ws[buf][wrow][wcol], wsrc, true);
        asm volatile("cp.async.commit_group;");
    };

    float acc[2][4][4] = {};

    issue(0);
    for (int c = 0; c < nchunks; c++) {
        if (c + 1 < nchunks) {
            issue(c + 1);
            asm volatile("cp.async.wait_group 1;");
        } else {
            asm volatile("cp.async.wait_group 0;");
        }
        __syncthreads();
        const int buf = c & 1;
        // this k-group handles kk = kg*16 and kg*16+8
        #pragma unroll
        for (int s = 0; s < 2; s++) {
            const int kk = kg * 16 + s * 8;
            uint32_t a[2][4];
            #pragma unroll
            for (int mt = 0; mt < 2; mt++) {
                const int r = warpRow + mt * 16 + g;
                a[mt][0] = f2tf32(As[buf][r][kk + tg]);
                a[mt][1] = f2tf32(As[buf][r + 8][kk + tg]);
                a[mt][2] = f2tf32(As[buf][r][kk + tg + 4]);
                a[mt][3] = f2tf32(As[buf][r + 8][kk + tg + 4]);
            }
            #pragma unroll
            for (int nt = 0; nt < 4; nt++) {
                uint32_t b0 = Ws[buf][kk + tg][nt * 8 + g];
                uint32_t b1 = Ws[buf][kk + tg + 4][nt * 8 + g];
                #pragma unroll
                for (int mt = 0; mt < 2; mt++) {
                    float* cc = acc[mt][nt];
                    asm volatile(
                        "mma.sync.aligned.m16n8k8.row.col.f32.tf32.tf32.f32 "
                        "{%0,%1,%2,%3}, {%4,%5,%6,%7}, {%8,%9}, {%0,%1,%2,%3};"
                        : "+f"(cc[0]), "+f"(cc[1]), "+f"(cc[2]), "+f"(cc[3])
                        : "r"(a[mt][0]), "r"(a[mt][1]), "r"(a[mt][2]), "r"(a[mt][3]),
                          "r"(b0), "r"(b1));
                }
            }
        }
        __syncthreads();
    }

    // ---- cross-k-group reduction via smem (reuse As as scratch) ----
    float* scratch = &As[0][0][0];   // 32 combos x 128 slots = 4096 floats
    if (kg == 1) {
        #pragma unroll
        for (int mt = 0; mt < 2; mt++)
            #pragma unroll
            for (int nt = 0; nt < 4; nt++)
                #pragma unroll
                for (int i = 0; i < 4; i++) {
                    int combo = (mt * 4 + nt) * 4 + i;
                    scratch[combo * 128 + mwarp * 32 + lane] = acc[mt][nt][i];
                }
    }
    __syncthreads();

    if (kg == 0) {
        #pragma unroll
        for (int nt = 0; nt < 4; nt++) {
            int lc = nt * 8 + 2 * tg;
            float b0 = bias[bn + lc];
            float b1 = bias[bn + lc + 1];
            #pragma unroll
            for (int mt = 0; mt < 2; mt++) {
                float* cc = acc[mt][nt];
                int base = ((mt * 4 + nt) * 4) * 128 + mwarp * 32 + lane;
                float v00 = cc[0] + scratch[base]       + b0;
                float v01 = cc[1] + scratch[base + 128] + b1;
                float v10 = cc[2] + scratch[base + 256] + b0;
                float v11 = cc[3] + scratch[base + 384] + b1;
                if (LEAKY) {
                    v00 = lrelu(v00); v01 = lrelu(v01);
                    v10 = lrelu(v10); v11 = lrelu(v11);
                }
                int r0 = blockRow + warpRow + mt * 16 + g;
                int r1 = r0 + 8;
                if (r0 < M)
                    *(float2*)(C + (size_t)r0 * ldC + cOff + bn + lc) = make_float2(v00, v01);
                if (r1 < M)
                    *(float2*)(C + (size_t)r1 * ldC + cOff + bn + lc) = make_float2(v10, v11);
            }
        }
    }
}

// fused 3-way projection: blockIdx.z selects (A, tf32-W, b, column offset)
struct ProjArgs {
    const float* A[3];
    const uint32_t* W[3];
    const float* b[3];
    int off[3];
};

__global__ void __launch_bounds__(256) proj_kernel(ProjArgs pa, float* __restrict__ C,
                                                   int M, int K) {
    int z = blockIdx.z;
    gemm_core<true>(pa.A[z], pa.W[z], nullptr, nullptr, pa.b[z], C,
                    M, K, 32, HID, pa.off[z], false);
}

template <bool DUAL, bool LEAKY>
__global__ void __launch_bounds__(256) gemm_tc_kernel(
    const float* __restrict__ A1, const uint32_t* __restrict__ W1,
    const float* __restrict__ A2, const uint32_t* __restrict__ W2,
    const float* __restrict__ bias, float* __restrict__ C,
    int M, int K, int ldW, int ldC, int cOff) {
    gemm_core<LEAKY>(A1, W1, A2, W2, bias, C, M, K, ldW, ldC, cOff, DUAL);
}

// ---------------- small feature projections: num_prop (6->32), num_category (11->32)
__global__ void __launch_bounds__(256) feat_small_kernel(
    const float* __restrict__ np, const float* __restrict__ nc,
    const float* __restrict__ Wnp, const float* __restrict__ bnp,
    const float* __restrict__ Wnc, const float* __restrict__ bnc,
    float* __restrict__ out)
{
    __shared__ float sWnp[6 * 32];
    __shared__ float sWnc[11 * 32];
    __shared__ float sb[64];
    int t = threadIdx.x;
    for (int i = t; i < 192; i += 256) sWnp[i] = Wnp[i];
    for (int i = t; i < 352; i += 256) sWnc[i] = Wnc[i];
    if (t < 32) sb[t] = bnp[t];
    else if (t < 64) sb[t] = bnc[t - 32];
    __syncthreads();

    int node = blockIdx.x * 8 + (t >> 5);
    int lane = t & 31;
    if (node >= NN) return;

    float a = sb[lane], c = sb[32 + lane];
    #pragma unroll
    for (int k = 0; k < 6; k++) a += np[(size_t)node * 6 + k] * sWnp[k * 32 + lane];
    #pragma unroll
    for (int k = 0; k < 11; k++) c += nc[(size_t)node * 11 + k] * sWnc[k * 32 + lane];
    out[(size_t)node * HID + lane] = lrelu(a);
    out[(size_t)node * HID + 32 + lane] = lrelu(c);
}

// ---------------- CSR build ----------------
__global__ void zero_deg_kernel() {
    int i = blockIdx.x * blockDim.x + threadIdx.x;
    if (i < NN) g_deg[i] = 0;
}

__global__ void count_deg_kernel(const void* __restrict__ ei, int E) {
    int e = blockIdx.x * blockDim.x + threadIdx.x;
    if (e < E) atomicAdd(&g_deg[edge_val(ei, E + e)], 1);
}

__global__ void scan_kernel() {
    __shared__ int part[1024];
    int t = threadIdx.x;
    const int chunk = (NN + 1023) / 1024;
    int s0 = t * chunk;
    int s1 = s0 + chunk; if (s1 > NN) s1 = NN; if (s0 > NN) s0 = NN;
    int s = 0;
    for (int i = s0; i < s1; i++) s += g_deg[i];
    part[t] = s;
    __syncthreads();
    for (int d = 1; d < 1024; d <<= 1) {
        int v = (t >= d) ? part[t - d] : 0;
        __syncthreads();
        part[t] += v;
        __syncthreads();
    }
    int excl = t ? part[t - 1] : 0;
    for (int i = s0; i < s1; i++) {
        g_offs[i] = excl;
        g_cursor[i] = excl;
        excl += g_deg[i];
    }
    if (t == 1023) g_offs[NN] = part[1023];
}

__global__ void fill_csr_kernel(const void* __restrict__ ei, int E) {
    int e = blockIdx.x * blockDim.x + threadIdx.x;
    if (e < E) {
        int d = edge_val(ei, E + e);
        int p = atomicAdd(&g_cursor[d], 1);
        g_csr[p] = edge_val(ei, e);
    }
}

// ---------------- mean aggregation: one warp per node ----------------
__global__ void __launch_bounds__(256) agg_kernel(const float* __restrict__ h,
                                                  float* __restrict__ mean)
{
    int w = (blockIdx.x * blockDim.x + threadIdx.x) >> 5;
    int lane = threadIdx.x & 31;
    if (w >= NN) return;
    int beg = g_offs[w], end = g_offs[w + 1];
    float a0 = 0.f, a1 = 0.f, a2 = 0.f, a3 = 0.f, a4 = 0.f;
    for (int e = beg; e < end; e++) {
        const float* row = h + (size_t)g_csr[e] * HID;
        a0 += row[lane];
        a1 += row[lane + 32];
        a2 += row[lane + 64];
        a3 += row[lane + 96];
        a4 += row[lane + 128];
    }
    int deg = end - beg;
    float inv = 1.f / (float)(deg > 0 ? deg : 1);
    float* m = mean + (size_t)w * HID;
    m[lane]       = a0 * inv;
    m[lane + 32]  = a1 * inv;
    m[lane + 64]  = a2 * inv;
    m[lane + 96]  = a3 * inv;
    m[lane + 128] = a4 * inv;
}

// ---------------- final 160->2 head: one warp per node ----------------
__global__ void __launch_bounds__(256) out2_kernel(
    const float* __restrict__ em, const float* __restrict__ W,
    const float* __restrict__ b, float* __restrict__ out)
{
    __shared__ float sW[320];
    int t = threadIdx.x;
    for (int i = t; i < 320; i += 256) sW[i] = W[i];
    __syncthreads();
    int node = blockIdx.x * 8 + (t >> 5);
    int lane = t & 31;
    if (node >= NN) return;
    float a0 = 0.f, a1 = 0.f;
    #pragma unroll
    for (int c = 0; c < 5; c++) {
        int k = lane + 32 * c;
        float v = em[(size_t)node * HID + k];
        a0 += v * sW[k * 2];
        a1 += v * sW[k * 2 + 1];
    }
    #pragma unroll
    for (int o = 16; o > 0; o >>= 1) {
        a0 += __shfl_down_sync(0xffffffffu, a0, o);
        a1 += __shfl_down_sync(0xffffffffu, a1, o);
    }
    if (lane == 0) {
        out[(size_t)node * 2]     = a0 + b[0];
        out[(size_t)node * 2 + 1] = a1 + b[1];
    }
}

// ---------------- launch ----------------
extern "C" void kernel_launch(void* const* d_in, const int* in_sizes, int n_in,
                              void* d_out, int out_size)
{
    const float* x        = (const float*)d_in[0];
    const void*  ei       = d_in[1];
    const float* num_prop = (const float*)d_in[2];
    const float* num_cat  = (const float*)d_in[3];
    const float* des      = (const float*)d_in[4];
    const float* tw       = (const float*)d_in[5];
    const float* W_des = (const float*)d_in[6];  const float* b_des = (const float*)d_in[7];
    const float* W_tw  = (const float*)d_in[8];  const float* b_tw  = (const float*)d_in[9];
    const float* W_txt = (const float*)d_in[10]; const float* b_txt = (const float*)d_in[11];
    const float* W_np  = (const float*)d_in[12]; const float* b_np  = (const float*)d_in[13];
    const float* W_nc  = (const float*)d_in[14]; const float* b_nc  = (const float*)d_in[15];
    const float* W_in  = (const float*)d_in[16]; const float* b_in  = (const float*)d_in[17];
    const float* W_l   = (const float*)d_in[18]; const float* b_l   = (const float*)d_in[19];
    const float* W_r   = (const float*)d_in[20];
    const float* W_o1  = (const float*)d_in[21]; const float* b_o1  = (const float*)d_in[22];
    const float* W_o2  = (const float*)d_in[23]; const float* b_o2  = (const float*)d_in[24];

    int E = in_sizes[1] / 2;
    if (E > EMAX) E = EMAX;

    float *feat, *h1, *mean, *h2;
    uint32_t* wtf;
    cudaGetSymbolAddress((void**)&feat, g_feat);
    cudaGetSymbolAddress((void**)&h1, g_h1);
    cudaGetSymbolAddress((void**)&mean, g_mean);
    cudaGetSymbolAddress((void**)&h2, g_h2);
    cudaGetSymbolAddress((void**)&wtf, g_wtf);

    float* outp = (float*)d_out;            // [N, 2]
    float* em   = (float*)d_out + 2 * NN;   // [N, 160]

    // weight preconversion offsets: W_des | W_tw | W_txt | W_in | W_l | W_r | W_o1
    WConvArgs wa;
    wa.src[0] = W_des; wa.src[1] = W_tw; wa.src[2] = W_txt;
    wa.src[3] = W_in;  wa.src[4] = W_l;  wa.src[5] = W_r; wa.src[6] = W_o1;
    int sizes[7] = {24576, 24576, 24576, 25600, 25600, 25600, 25600};
    wa.off[0] = 0;
    for (int i = 0; i < 7; i++) wa.off[i + 1] = wa.off[i] + sizes[i];
    const uint32_t* tW_des = wtf + wa.off[0];
    const uint32_t* tW_tw  = wtf + wa.off[1];
    const uint32_t* tW_txt = wtf + wa.off[2];
    const uint32_t* tW_in  = wtf + wa.off[3];
    const uint32_t* tW_l   = wtf + wa.off[4];
    const uint32_t* tW_r   = wtf + wa.off[5];
    const uint32_t* tW_o1  = wtf + wa.off[6];
    wconv_kernel<<<(wa.off[7] + 255) / 256, 256>>>(wa);

    dim3 gProj((NN + 127) / 128, 1, 3);
    dim3 g128x5((NN + 127) / 128, 5);
    int gNode8 = (NN + 7) / 8;
    int gEdge = (E + 255) / 256;

    // feature encoder -> g_feat [N,160] (cols: n|c|d|tw|t)
    feat_small_kernel<<<gNode8, 256>>>(num_prop, num_cat, W_np, b_np, W_nc, b_nc, feat);

    ProjArgs pa;
    pa.A[0] = des; pa.W[0] = tW_des; pa.b[0] = b_des; pa.off[0] = 64;
    pa.A[1] = tw;  pa.W[1] = tW_tw;  pa.b[1] = b_tw;  pa.off[1] = 96;
    pa.A[2] = x;   pa.W[2] = tW_txt; pa.b[2] = b_txt; pa.off[2] = 128;
    proj_kernel<<<gProj, 256>>>(pa, feat, NN, 768);

    // h1 = leaky(feat @ W_in + b_in)
    gemm_tc_kernel<false, true><<<g128x5, 256>>>(feat, tW_in, nullptr, nullptr, b_in, h1, NN, HID, HID, HID, 0);

    // CSR build (per-launch, deterministic detection of edge dtype)
    detect_kernel<<<1, 256>>>(ei, E);
    zero_deg_kernel<<<(NN + 255) / 256, 256>>>();
    count_deg_kernel<<<gEdge, 256>>>(ei, E);
    scan_kernel<<<1, 1024>>>();
    fill_csr_kernel<<<gEdge, 256>>>(ei, E);

    // conv1: h2 = mean(h1) @ W_l + b_l + h1 @ W_r
    agg_kernel<<<gNode8, 256>>>(h1, mean);
    gemm_tc_kernel<true, false><<<g128x5, 256>>>(mean, tW_l, h1, tW_r, b_l, h2, NN, HID, HID, HID, 0);

    // conv2: h1 = mean(h2) @ W_l + b_l + h2 @ W_r
    agg_kernel<<<gNode8, 256>>>(h2, mean);
    gemm_tc_kernel<true, false><<<g128x5, 256>>>(mean, tW_l, h2, tW_r, b_l, h1, NN, HID, HID, HID, 0);

    // em = leaky(h1 @ W_o1 + b_o1), written directly into d_out
    gemm_tc_kernel<false, true><<<g128x5, 256>>>(h1, tW_o1, nullptr, nullptr, b_o1, em, NN, HID, HID, HID, 0);

    // out = em @ W_o2 + b_o2
    out2_kernel<<<gNode8, 256>>>(em, W_o2, b_o2, outp);
}